// round 5
// baseline (speedup 1.0000x reference)
#include <cuda_runtime.h>
#include <cuda_bf16.h>
#include <cstdint>

#define N_NODES 100000
#define N_EDGES 1600000
#define IN_CH   128
#define HEADS   4
#define OUT_CH  32
#define HC      128
#define NEG_SLOPE 0.2f
#define EPS_F 1e-16f

#define NB_SCAN ((N_NODES + 255) / 256)   // 391 scan blocks

// ---------------- scratch (device globals; no allocation allowed) ----------
__device__ float g_xl[(size_t)N_NODES * HC];
__device__ float g_xr[(size_t)N_NODES * HC];
__device__ int   g_deg[N_NODES];
__device__ int   g_tmp[N_NODES];        // per-chunk inclusive scan
__device__ int   g_cursor[N_NODES];     // rowstart before bucket; rowend after
__device__ int   g_part[NB_SCAN];       // block totals
__device__ int   g_part2[NB_SCAN];      // exclusive scan of totals
__device__ int   g_ssrc[N_EDGES];       // srcs bucketed by dst

__device__ __forceinline__ float lrelu(float v) {
    return fmaxf(v, 0.f) + NEG_SLOPE * fminf(v, 0.f);
}
__device__ __forceinline__ uint32_t to_tf32(float f) {
    uint32_t o;
    asm("cvt.rna.tf32.f32 %0, %1;" : "=r"(o) : "f"(f));
    return o;
}

// ---------------- K0: zero degree histogram ---------------------------------
__global__ void k_zero() {
    int i = blockIdx.x * 256 + threadIdx.x;
    if (i < N_NODES) g_deg[i] = 0;
}

// ---------------- K1: degree histogram --------------------------------------
__global__ __launch_bounds__(256) void k_degree(const int* __restrict__ ei) {
    int e = blockIdx.x * 256 + threadIdx.x;
    if (e < N_EDGES) atomicAdd(&g_deg[ei[N_EDGES + e]], 1);
}

// ---------------- K2a/b/c: two-level exclusive scan of degrees --------------
__global__ __launch_bounds__(256) void k_scan1() {
    __shared__ int s[256];
    int b = blockIdx.x, tid = threadIdx.x;
    int i = b * 256 + tid;
    int v = (i < N_NODES) ? g_deg[i] : 0;
    s[tid] = v;
    __syncthreads();
#pragma unroll
    for (int off = 1; off < 256; off <<= 1) {
        int t = (tid >= off) ? s[tid - off] : 0;
        __syncthreads();
        s[tid] += t;
        __syncthreads();
    }
    if (i < N_NODES) g_tmp[i] = s[tid];
    if (tid == 255) g_part[b] = s[255];
}
__global__ __launch_bounds__(512) void k_scan2() {
    __shared__ int s[512];
    int tid = threadIdx.x;
    int v = (tid < NB_SCAN) ? g_part[tid] : 0;
    s[tid] = v;
    __syncthreads();
#pragma unroll
    for (int off = 1; off < 512; off <<= 1) {
        int t = (tid >= off) ? s[tid - off] : 0;
        __syncthreads();
        s[tid] += t;
        __syncthreads();
    }
    if (tid < NB_SCAN) g_part2[tid] = s[tid] - v;   // exclusive
}
__global__ __launch_bounds__(256) void k_scan3() {
    int i = blockIdx.x * 256 + threadIdx.x;
    if (i >= N_NODES) return;
    g_cursor[i] = g_tmp[i] - g_deg[i] + g_part2[i >> 8];   // rowstart
}

// ---------------- K3: bucket edges by destination ----------------------------
__global__ __launch_bounds__(256) void k_bucket(const int* __restrict__ ei) {
    int e = blockIdx.x * 256 + threadIdx.x;
    if (e >= N_EDGES) return;
    int src = ei[e];
    int dst = ei[N_EDGES + e];
    int pos = atomicAdd(&g_cursor[dst], 1);
    g_ssrc[pos] = src;
}

// ---------------- K4: fused dual GEMM via tf32 tensor-core mma --------------
__global__ __launch_bounds__(256) void k_gemm(
    const float* __restrict__ X,
    const float* __restrict__ Wl,
    const float* __restrict__ Wr)
{
    __shared__ uint32_t xs[64][36];
    __shared__ uint32_t ws[32][264];

    const int tid  = threadIdx.x;
    const int warp = tid >> 5;
    const int lane = tid & 31;
    const int r     = warp & 3;
    const int cHalf = warp >> 2;
    const int row0 = blockIdx.x * 64;
    const int qr = lane >> 2;
    const int ql = lane & 3;

    float c[16][4];
#pragma unroll
    for (int j = 0; j < 16; j++)
#pragma unroll
        for (int q = 0; q < 4; q++) c[j][q] = 0.f;

    for (int chunk = 0; chunk < 4; chunk++) {
        const int k0 = chunk * 32;
        if (chunk) __syncthreads();
#pragma unroll
        for (int i = 0; i < 2; i++) {
            int li = tid + i * 256;
            int m  = li >> 3;
            int kq = (li & 7) * 4;
            float4 v = make_float4(0.f, 0.f, 0.f, 0.f);
            if (row0 + m < N_NODES)
                v = *(const float4*)&X[(size_t)(row0 + m) * IN_CH + k0 + kq];
            xs[m][kq + 0] = to_tf32(v.x); xs[m][kq + 1] = to_tf32(v.y);
            xs[m][kq + 2] = to_tf32(v.z); xs[m][kq + 3] = to_tf32(v.w);
        }
#pragma unroll
        for (int i = 0; i < 8; i++) {
            int li = tid + i * 256;
            int k  = li >> 6;
            int cq = (li & 63) * 4;
            const float* Wsrc = (cq < 128) ? Wl : Wr;
            int cc = (cq < 128) ? cq : (cq - 128);
            float4 v = *(const float4*)&Wsrc[(size_t)(k0 + k) * HC + cc];
            ws[k][cq + 0] = to_tf32(v.x); ws[k][cq + 1] = to_tf32(v.y);
            ws[k][cq + 2] = to_tf32(v.z); ws[k][cq + 3] = to_tf32(v.w);
        }
        __syncthreads();

#pragma unroll
        for (int ks = 0; ks < 4; ks++) {
            const int kk = ks * 8;
            uint32_t a0 = xs[r * 16 + qr    ][kk + ql    ];
            uint32_t a1 = xs[r * 16 + qr + 8][kk + ql    ];
            uint32_t a2 = xs[r * 16 + qr    ][kk + ql + 4];
            uint32_t a3 = xs[r * 16 + qr + 8][kk + ql + 4];
#pragma unroll
            for (int j = 0; j < 16; j++) {
                int nb = cHalf * 128 + j * 8 + qr;
                uint32_t b0 = ws[kk + ql    ][nb];
                uint32_t b1 = ws[kk + ql + 4][nb];
                asm volatile(
                    "mma.sync.aligned.m16n8k8.row.col.f32.tf32.tf32.f32 "
                    "{%0,%1,%2,%3}, {%4,%5,%6,%7}, {%8,%9}, {%0,%1,%2,%3};"
                    : "+f"(c[j][0]), "+f"(c[j][1]), "+f"(c[j][2]), "+f"(c[j][3])
                    : "r"(a0), "r"(a1), "r"(a2), "r"(a3), "r"(b0), "r"(b1));
            }
        }
    }

    float* Y = cHalf ? g_xr : g_xl;
    const int rbase = row0 + r * 16 + qr;
#pragma unroll
    for (int j = 0; j < 16; j++) {
        int col = j * 8 + 2 * ql;
        if (rbase < N_NODES)
            *(float2*)&Y[(size_t)rbase * HC + col] = make_float2(c[j][0], c[j][1]);
        if (rbase + 8 < N_NODES)
            *(float2*)&Y[(size_t)(rbase + 8) * HC + col] = make_float2(c[j][2], c[j][3]);
    }
}

// ---------------- K5: per-node online-softmax aggregation (4-way ILP) -------
// one warp per node; 4 independent online-softmax states merged at the end.
#define HEAD_REDUCE(p) \
    p += __shfl_xor_sync(0xffffffffu, p, 1); \
    p += __shfl_xor_sync(0xffffffffu, p, 2); \
    p += __shfl_xor_sync(0xffffffffu, p, 4);

#define LOGIT(p, a) { \
    p = lrelu(a.x + xr4.x) * t.x; \
    p = fmaf(lrelu(a.y + xr4.y), t.y, p); \
    p = fmaf(lrelu(a.z + xr4.z), t.z, p); \
    p = fmaf(lrelu(a.w + xr4.w), t.w, p); }

#define UPD(m, d, A, p, a) { \
    float nm = fmaxf(m, p); \
    float s  = __expf(m - nm); \
    float ee = __expf(p - nm); \
    d = d * s + ee; \
    A.x = fmaf(A.x, s, ee * a.x); \
    A.y = fmaf(A.y, s, ee * a.y); \
    A.z = fmaf(A.z, s, ee * a.z); \
    A.w = fmaf(A.w, s, ee * a.w); \
    m = nm; }

__global__ __launch_bounds__(256) void k_aggregate(
    const float* __restrict__ att,
    const float* __restrict__ bias,
    float* __restrict__ out)
{
    int node = blockIdx.x * 8 + (threadIdx.x >> 5);
    if (node >= N_NODES) return;
    int lane = threadIdx.x & 31;

    float4 xr4 = *(const float4*)&g_xr[(size_t)node * HC + lane * 4];
    float4 t   = *(const float4*)&att[lane * 4];

    float  m0 = -1e30f, m1 = -1e30f, m2 = -1e30f, m3 = -1e30f;
    float  d0 = 0.f, d1 = 0.f, d2 = 0.f, d3 = 0.f;
    float4 A0 = make_float4(0.f,0.f,0.f,0.f), A1 = A0, A2 = A0, A3 = A0;

    int n     = g_deg[node];
    int start = g_cursor[node] - n;   // bucket left cursor at row end

    for (int base = 0; base < n; base += 32) {
        int cnt = min(32, n - base);
        int mysrc = (lane < cnt) ? g_ssrc[start + base + lane] : 0;
        int j = 0;
        for (; j + 4 <= cnt; j += 4) {
            int s0 = __shfl_sync(0xffffffffu, mysrc, j);
            int s1 = __shfl_sync(0xffffffffu, mysrc, j + 1);
            int s2 = __shfl_sync(0xffffffffu, mysrc, j + 2);
            int s3 = __shfl_sync(0xffffffffu, mysrc, j + 3);
            float4 a0 = *(const float4*)&g_xl[(size_t)s0 * HC + lane * 4];
            float4 a1 = *(const float4*)&g_xl[(size_t)s1 * HC + lane * 4];
            float4 a2 = *(const float4*)&g_xl[(size_t)s2 * HC + lane * 4];
            float4 a3 = *(const float4*)&g_xl[(size_t)s3 * HC + lane * 4];

            float p0, p1, p2, p3;
            LOGIT(p0, a0); LOGIT(p1, a1); LOGIT(p2, a2); LOGIT(p3, a3);
            HEAD_REDUCE(p0); HEAD_REDUCE(p1); HEAD_REDUCE(p2); HEAD_REDUCE(p3);

            UPD(m0, d0, A0, p0, a0);
            UPD(m1, d1, A1, p1, a1);
            UPD(m2, d2, A2, p2, a2);
            UPD(m3, d3, A3, p3, a3);
        }
        for (; j < cnt; j++) {
            int s0 = __shfl_sync(0xffffffffu, mysrc, j);
            float4 a0 = *(const float4*)&g_xl[(size_t)s0 * HC + lane * 4];
            float p0;
            LOGIT(p0, a0);
            HEAD_REDUCE(p0);
            UPD(m0, d0, A0, p0, a0);
        }
    }

    // merge the 4 online states
    float M = fmaxf(fmaxf(m0, m1), fmaxf(m2, m3));
    float w0 = __expf(m0 - M), w1 = __expf(m1 - M);
    float w2 = __expf(m2 - M), w3 = __expf(m3 - M);
    float D = d0 * w0 + d1 * w1 + d2 * w2 + d3 * w3;
    float4 ACC;
    ACC.x = A0.x * w0 + A1.x * w1 + A2.x * w2 + A3.x * w3;
    ACC.y = A0.y * w0 + A1.y * w1 + A2.y * w2 + A3.y * w3;
    ACC.z = A0.z * w0 + A1.z * w1 + A2.z * w2 + A3.z * w3;
    ACC.w = A0.w * w0 + A1.w * w1 + A2.w * w2 + A3.w * w3;

    float inv = 1.f / (D + EPS_F);
    float4 b4 = *(const float4*)&bias[lane * 4];
    float4 o;
    o.x = fmaf(ACC.x, inv, b4.x);
    o.y = fmaf(ACC.y, inv, b4.y);
    o.z = fmaf(ACC.z, inv, b4.z);
    o.w = fmaf(ACC.w, inv, b4.w);
    *(float4*)&out[(size_t)node * HC + lane * 4] = o;
}

// ---------------- launch ----------------------------------------------------
extern "C" void kernel_launch(void* const* d_in, const int* in_sizes, int n_in,
                              void* d_out, int out_size)
{
    const float* x    = (const float*)d_in[0];
    const int*   ei   = (const int*)d_in[1];
    const float* Wl   = (const float*)d_in[2];
    const float* Wr   = (const float*)d_in[3];
    const float* att  = (const float*)d_in[4];
    const float* bias = (const float*)d_in[5];
    float* out = (float*)d_out;

    k_zero<<<NB_SCAN, 256>>>();
    k_degree<<<(N_EDGES + 255) / 256, 256>>>(ei);
    k_scan1<<<NB_SCAN, 256>>>();
    k_scan2<<<1, 512>>>();
    k_scan3<<<NB_SCAN, 256>>>();
    k_bucket<<<(N_EDGES + 255) / 256, 256>>>(ei);

    k_gemm<<<(N_NODES + 63) / 64, 256>>>(x, Wl, Wr);

    k_aggregate<<<(N_NODES + 7) / 8, 256>>>(att, bias, out);
}

// round 6
// speedup vs baseline: 1.1139x; 1.1139x over previous
#include <cuda_runtime.h>
#include <cuda_bf16.h>
#include <cstdint>

#define N_NODES 100000
#define N_EDGES 1600000
#define IN_CH   128
#define HEADS   4
#define OUT_CH  32
#define HC      128
#define NEG_SLOPE 0.2f
#define EPS_F 1e-16f

#define NB_SCAN ((N_NODES + 255) / 256)   // 391 scan blocks

// ---------------- scratch (device globals; no allocation allowed) ----------
__device__ float g_xl[(size_t)N_NODES * HC];
__device__ float g_xr[(size_t)N_NODES * HC];
__device__ int   g_deg[N_NODES];
__device__ int   g_tmp[N_NODES];        // per-chunk inclusive scan
__device__ int   g_cursor[N_NODES];     // rowstart before bucket; rowend after
__device__ int   g_part[NB_SCAN];       // block totals
__device__ int   g_part2[NB_SCAN];      // exclusive scan of totals
__device__ int   g_ssrc[N_EDGES];       // srcs bucketed by dst

__device__ __forceinline__ float lrelu(float v) {
    return fmaxf(v, 0.f) + NEG_SLOPE * fminf(v, 0.f);
}
__device__ __forceinline__ uint32_t to_tf32(float f) {
    uint32_t o;
    asm("cvt.rna.tf32.f32 %0, %1;" : "=r"(o) : "f"(f));
    return o;
}

// ---------------- K0: zero degree histogram ---------------------------------
__global__ void k_zero() {
    int i = blockIdx.x * 256 + threadIdx.x;
    if (i < N_NODES) g_deg[i] = 0;
}

// ---------------- K1: degree histogram --------------------------------------
__global__ __launch_bounds__(256) void k_degree(const int* __restrict__ ei) {
    int e = blockIdx.x * 256 + threadIdx.x;
    if (e < N_EDGES) atomicAdd(&g_deg[ei[N_EDGES + e]], 1);
}

// ---------------- K2a/b/c: two-level exclusive scan of degrees --------------
__global__ __launch_bounds__(256) void k_scan1() {
    __shared__ int s[256];
    int b = blockIdx.x, tid = threadIdx.x;
    int i = b * 256 + tid;
    int v = (i < N_NODES) ? g_deg[i] : 0;
    s[tid] = v;
    __syncthreads();
#pragma unroll
    for (int off = 1; off < 256; off <<= 1) {
        int t = (tid >= off) ? s[tid - off] : 0;
        __syncthreads();
        s[tid] += t;
        __syncthreads();
    }
    if (i < N_NODES) g_tmp[i] = s[tid];
    if (tid == 255) g_part[b] = s[255];
}
__global__ __launch_bounds__(512) void k_scan2() {
    __shared__ int s[512];
    int tid = threadIdx.x;
    int v = (tid < NB_SCAN) ? g_part[tid] : 0;
    s[tid] = v;
    __syncthreads();
#pragma unroll
    for (int off = 1; off < 512; off <<= 1) {
        int t = (tid >= off) ? s[tid - off] : 0;
        __syncthreads();
        s[tid] += t;
        __syncthreads();
    }
    if (tid < NB_SCAN) g_part2[tid] = s[tid] - v;   // exclusive
}
__global__ __launch_bounds__(256) void k_scan3() {
    int i = blockIdx.x * 256 + threadIdx.x;
    if (i >= N_NODES) return;
    g_cursor[i] = g_tmp[i] - g_deg[i] + g_part2[i >> 8];   // rowstart
}

// ---------------- K3: bucket edges by destination ----------------------------
__global__ __launch_bounds__(256) void k_bucket(const int* __restrict__ ei) {
    int e = blockIdx.x * 256 + threadIdx.x;
    if (e >= N_EDGES) return;
    int src = ei[e];
    int dst = ei[N_EDGES + e];
    int pos = atomicAdd(&g_cursor[dst], 1);
    g_ssrc[pos] = src;
}

// ---------------- K4: fused dual GEMM via tf32 tensor-core mma --------------
__global__ __launch_bounds__(256) void k_gemm(
    const float* __restrict__ X,
    const float* __restrict__ Wl,
    const float* __restrict__ Wr)
{
    __shared__ uint32_t xs[64][36];
    __shared__ uint32_t ws[32][264];

    const int tid  = threadIdx.x;
    const int warp = tid >> 5;
    const int lane = tid & 31;
    const int r     = warp & 3;
    const int cHalf = warp >> 2;
    const int row0 = blockIdx.x * 64;
    const int qr = lane >> 2;
    const int ql = lane & 3;

    float c[16][4];
#pragma unroll
    for (int j = 0; j < 16; j++)
#pragma unroll
        for (int q = 0; q < 4; q++) c[j][q] = 0.f;

    for (int chunk = 0; chunk < 4; chunk++) {
        const int k0 = chunk * 32;
        if (chunk) __syncthreads();
#pragma unroll
        for (int i = 0; i < 2; i++) {
            int li = tid + i * 256;
            int m  = li >> 3;
            int kq = (li & 7) * 4;
            float4 v = make_float4(0.f, 0.f, 0.f, 0.f);
            if (row0 + m < N_NODES)
                v = *(const float4*)&X[(size_t)(row0 + m) * IN_CH + k0 + kq];
            xs[m][kq + 0] = to_tf32(v.x); xs[m][kq + 1] = to_tf32(v.y);
            xs[m][kq + 2] = to_tf32(v.z); xs[m][kq + 3] = to_tf32(v.w);
        }
#pragma unroll
        for (int i = 0; i < 8; i++) {
            int li = tid + i * 256;
            int k  = li >> 6;
            int cq = (li & 63) * 4;
            const float* Wsrc = (cq < 128) ? Wl : Wr;
            int cc = (cq < 128) ? cq : (cq - 128);
            float4 v = *(const float4*)&Wsrc[(size_t)(k0 + k) * HC + cc];
            ws[k][cq + 0] = to_tf32(v.x); ws[k][cq + 1] = to_tf32(v.y);
            ws[k][cq + 2] = to_tf32(v.z); ws[k][cq + 3] = to_tf32(v.w);
        }
        __syncthreads();

#pragma unroll
        for (int ks = 0; ks < 4; ks++) {
            const int kk = ks * 8;
            uint32_t a0 = xs[r * 16 + qr    ][kk + ql    ];
            uint32_t a1 = xs[r * 16 + qr + 8][kk + ql    ];
            uint32_t a2 = xs[r * 16 + qr    ][kk + ql + 4];
            uint32_t a3 = xs[r * 16 + qr + 8][kk + ql + 4];
#pragma unroll
            for (int j = 0; j < 16; j++) {
                int nb = cHalf * 128 + j * 8 + qr;
                uint32_t b0 = ws[kk + ql    ][nb];
                uint32_t b1 = ws[kk + ql + 4][nb];
                asm volatile(
                    "mma.sync.aligned.m16n8k8.row.col.f32.tf32.tf32.f32 "
                    "{%0,%1,%2,%3}, {%4,%5,%6,%7}, {%8,%9}, {%0,%1,%2,%3};"
                    : "+f"(c[j][0]), "+f"(c[j][1]), "+f"(c[j][2]), "+f"(c[j][3])
                    : "r"(a0), "r"(a1), "r"(a2), "r"(a3), "r"(b0), "r"(b1));
            }
        }
    }

    float* Y = cHalf ? g_xr : g_xl;
    const int rbase = row0 + r * 16 + qr;
#pragma unroll
    for (int j = 0; j < 16; j++) {
        int col = j * 8 + 2 * ql;
        if (rbase < N_NODES)
            *(float2*)&Y[(size_t)rbase * HC + col] = make_float2(c[j][0], c[j][1]);
        if (rbase + 8 < N_NODES)
            *(float2*)&Y[(size_t)(rbase + 8) * HC + col] = make_float2(c[j][2], c[j][3]);
    }
}

// ---------------- K5: per-node online-softmax aggregation -------------------
// one warp per node (R4 version — known-good balance of regs vs ILP)
__global__ __launch_bounds__(256) void k_aggregate(
    const float* __restrict__ att,
    const float* __restrict__ bias,
    float* __restrict__ out)
{
    int node = blockIdx.x * 8 + (threadIdx.x >> 5);
    if (node >= N_NODES) return;
    int lane = threadIdx.x & 31;

    float4 xr4 = *(const float4*)&g_xr[(size_t)node * HC + lane * 4];
    float4 t   = *(const float4*)&att[lane * 4];

    float m = -1e30f, d = 0.f;
    float4 acc = make_float4(0.f, 0.f, 0.f, 0.f);

    int n     = g_deg[node];
    int start = g_cursor[node] - n;   // bucket left cursor at row end

    for (int base = 0; base < n; base += 32) {
        int cnt = min(32, n - base);
        int mysrc = (lane < cnt) ? g_ssrc[start + base + lane] : 0;
        for (int j = 0; j < cnt; j++) {
            int src = __shfl_sync(0xffffffffu, mysrc, j);
            float4 a = *(const float4*)&g_xl[(size_t)src * HC + lane * 4];

            float p = lrelu(a.x + xr4.x) * t.x;
            p = fmaf(lrelu(a.y + xr4.y), t.y, p);
            p = fmaf(lrelu(a.z + xr4.z), t.z, p);
            p = fmaf(lrelu(a.w + xr4.w), t.w, p);
            p += __shfl_xor_sync(0xffffffffu, p, 1);
            p += __shfl_xor_sync(0xffffffffu, p, 2);
            p += __shfl_xor_sync(0xffffffffu, p, 4);

            float nm = fmaxf(m, p);
            float s  = __expf(m - nm);
            float ee = __expf(p - nm);
            d = d * s + ee;
            acc.x = fmaf(acc.x, s, ee * a.x);
            acc.y = fmaf(acc.y, s, ee * a.y);
            acc.z = fmaf(acc.z, s, ee * a.z);
            acc.w = fmaf(acc.w, s, ee * a.w);
            m = nm;
        }
    }

    float inv = 1.f / (d + EPS_F);
    float4 b4 = *(const float4*)&bias[lane * 4];
    float4 o;
    o.x = fmaf(acc.x, inv, b4.x);
    o.y = fmaf(acc.y, inv, b4.y);
    o.z = fmaf(acc.z, inv, b4.z);
    o.w = fmaf(acc.w, inv, b4.w);
    *(float4*)&out[(size_t)node * HC + lane * 4] = o;
}

// ---------------- launch ----------------------------------------------------
// GEMM branch (depends on x, W) is forked onto a side stream and runs
// concurrently with the CSR-build branch (depends on edge_index only).
// Event fork/join is the standard graph-capture DAG pattern.
extern "C" void kernel_launch(void* const* d_in, const int* in_sizes, int n_in,
                              void* d_out, int out_size)
{
    const float* x    = (const float*)d_in[0];
    const int*   ei   = (const int*)d_in[1];
    const float* Wl   = (const float*)d_in[2];
    const float* Wr   = (const float*)d_in[3];
    const float* att  = (const float*)d_in[4];
    const float* bias = (const float*)d_in[5];
    float* out = (float*)d_out;

    static cudaStream_t s_side = nullptr;
    static cudaEvent_t  ev_fork = nullptr, ev_join = nullptr;
    if (s_side == nullptr) {
        cudaStreamCreateWithFlags(&s_side, cudaStreamNonBlocking);
        cudaEventCreateWithFlags(&ev_fork, cudaEventDisableTiming);
        cudaEventCreateWithFlags(&ev_join, cudaEventDisableTiming);
    }

    // fork: GEMM on side stream
    cudaEventRecord(ev_fork, (cudaStream_t)0);
    cudaStreamWaitEvent(s_side, ev_fork, 0);
    k_gemm<<<(N_NODES + 63) / 64, 256, 0, s_side>>>(x, Wl, Wr);
    cudaEventRecord(ev_join, s_side);

    // CSR build on main stream (concurrent with GEMM)
    k_zero<<<NB_SCAN, 256>>>();
    k_degree<<<(N_EDGES + 255) / 256, 256>>>(ei);
    k_scan1<<<NB_SCAN, 256>>>();
    k_scan2<<<1, 512>>>();
    k_scan3<<<NB_SCAN, 256>>>();
    k_bucket<<<(N_EDGES + 255) / 256, 256>>>(ei);

    // join: aggregate needs both branches
    cudaStreamWaitEvent((cudaStream_t)0, ev_join, 0);
    k_aggregate<<<(N_NODES + 7) / 8, 256>>>(att, bias, out);
}